// round 10
// baseline (speedup 1.0000x reference)
#include <cuda_runtime.h>
#include <cuda_fp16.h>

#define BATCH     32
#define CHANNELS  3
#define HIMG      512
#define WIMG      512
#define PLANE     (HIMG * WIMG)
#define PXTOT     (BATCH * PLANE)
#define THREADS   256
#define ROWS_PER_BLOCK 4
#define NBLOCKS   (BATCH * HIMG / ROWS_PER_BLOCK)   // 4096 total main blocks
#define INV_NELEM (1.0f / (float)(BATCH * CHANNELS * HIMG * WIMG))

#define NCHUNK            4
#define PRE_BLOCKS_TOTAL  (PXTOT / 4 / THREADS)      // 8192
#define PRE_BLOCKS_CHUNK  (PRE_BLOCKS_TOTAL / NCHUNK) // 2048
#define MAIN_BLOCKS_CHUNK (NBLOCKS / NCHUNK)          // 1024

// Padded interleaved image: 1-px zero frame (never written; __device__
// globals zero-init at module load -> permanent zero-padding for edge taps).
#define PSTRIDE   516
#define PROWS     514
#define PPLANE    (PROWS * PSTRIDE)
__device__ __half2      g_img[BATCH * PPLANE * 2];   // ~67.9 MB
__device__ float        g_acc;
__device__ unsigned int g_ticket;

// ---------------------------------------------------------------------------
// Prepass (chunked): planar fp32 [B,3,H,W] -> padded interleaved fp16x4
// ---------------------------------------------------------------------------
__global__ void __launch_bounds__(THREADS)
interleave_kernel(const float* __restrict__ I, int chunk) {
    int t   = (chunk * PRE_BLOCKS_CHUNK + blockIdx.x) * blockDim.x + threadIdx.x;
    int px  = t << 2;
    int b   = px >> 18;
    int off = px & (PLANE - 1);
    int y   = off >> 9;
    int x   = off & (WIMG - 1);
    const float* base = I + (size_t)b * (CHANNELS * PLANE) + off;
    float4 c0 = *(const float4*)(base);
    float4 c1 = *(const float4*)(base + PLANE);
    float4 c2 = *(const float4*)(base + 2 * PLANE);

    __half2 o[8];
    o[0] = __floats2half2_rn(c0.x, c1.x);
    o[1] = __floats2half2_rn(c2.x, 0.0f);
    o[2] = __floats2half2_rn(c0.y, c1.y);
    o[3] = __floats2half2_rn(c2.y, 0.0f);
    o[4] = __floats2half2_rn(c0.z, c1.z);
    o[5] = __floats2half2_rn(c2.z, 0.0f);
    o[6] = __floats2half2_rn(c0.w, c1.w);
    o[7] = __floats2half2_rn(c2.w, 0.0f);

    size_t dpx = (size_t)b * PPLANE + (y + 1) * PSTRIDE + (x + 2);
    uint4* dst = reinterpret_cast<uint4*>(g_img + dpx * 2);
    dst[0] = *reinterpret_cast<uint4*>(&o[0]);
    dst[1] = *reinterpret_cast<uint4*>(&o[4]);
}

// ---------------------------------------------------------------------------
// 3x3 inverse via adjugate; X,Y rows prescaled by W/(W-1)
// ---------------------------------------------------------------------------
#define CSCALE (512.0f / 511.0f)

__device__ __forceinline__ void invert3x3s(const float* __restrict__ m,
                                           float* __restrict__ inv) {
    float c00 = m[4] * m[8] - m[5] * m[7];
    float c01 = m[5] * m[6] - m[3] * m[8];
    float c02 = m[3] * m[7] - m[4] * m[6];
    float det = m[0] * c00 + m[1] * c01 + m[2] * c02;
    float id  = CSCALE / det;
    float idz = 1.0f / det;
    inv[0] = c00 * id;
    inv[1] = (m[2] * m[7] - m[1] * m[8]) * id;
    inv[2] = (m[1] * m[5] - m[2] * m[4]) * id;
    inv[3] = c01 * id;
    inv[4] = (m[0] * m[8] - m[2] * m[6]) * id;
    inv[5] = (m[2] * m[3] - m[0] * m[5]) * id;
    inv[6] = c02 * idz;
    inv[7] = (m[1] * m[6] - m[0] * m[7]) * idz;
    inv[8] = (m[0] * m[4] - m[1] * m[3]) * idz;
}

__device__ __forceinline__ float frcp(float x) {
    float r;
    asm("rcp.approx.f32 %0, %1;" : "=f"(r) : "f"(x));
    return r;
}

// ---------------------------------------------------------------------------
// One bilinear sample: unconditional LDG.64 x4; invalid samples redirected
// to the permanently-zero border corner.
// ---------------------------------------------------------------------------
__device__ __forceinline__ void sample3h(const uint2* __restrict__ img,
                                         float X, float Y, float Z,
                                         __half2& a01, __half2& a2) {
    float iz = frcp(Z);
    float sx = fmaf(X, iz, -0.5f);
    float sy = fmaf(Y, iz, -0.5f);
    sx = fminf(fmaxf(sx, -2.0f), 513.0f);
    sy = fminf(fmaxf(sy, -2.0f), 513.0f);
    float x0f = floorf(sx), y0f = floorf(sy);
    int x0 = (int)x0f, y0 = (int)y0f;
    bool valid = ((unsigned)(x0 + 1) < 513u) & ((unsigned)(y0 + 1) < 513u);
    float wx1 = sx - x0f, wx0 = 1.0f - wx1;
    float wy1 = sy - y0f, wy0 = 1.0f - wy1;
    int o = y0 * PSTRIDE + x0;
    o = valid ? o : -(PSTRIDE + 2);

    __half2 hwx  = __floats2half2_rn(wx0, wx1);
    __half2 hwy0 = __float2half2_rn(wy0);
    __half2 hwy1 = __float2half2_rn(wy1);
    __half2 wr0  = __hmul2(hwx, hwy0);    // (w00, w10)
    __half2 wr1  = __hmul2(hwx, hwy1);    // (w01, w11)
    __half2 w00 = __half2half2(__low2half(wr0));
    __half2 w10 = __half2half2(__high2half(wr0));
    __half2 w01 = __half2half2(__low2half(wr1));
    __half2 w11 = __half2half2(__high2half(wr1));

    const uint2* p = img + o + (PSTRIDE + 2);
    uint2 v00 = __ldg(p);
    uint2 v10 = __ldg(p + 1);
    uint2 v01 = __ldg(p + PSTRIDE);
    uint2 v11 = __ldg(p + PSTRIDE + 1);

    a01 = __hmul2(*reinterpret_cast<__half2*>(&v00.x), w00);
    a2  = __hmul2(*reinterpret_cast<__half2*>(&v00.y), w00);
    a01 = __hfma2(*reinterpret_cast<__half2*>(&v10.x), w10, a01);
    a2  = __hfma2(*reinterpret_cast<__half2*>(&v10.y), w10, a2);
    a01 = __hfma2(*reinterpret_cast<__half2*>(&v01.x), w01, a01);
    a2  = __hfma2(*reinterpret_cast<__half2*>(&v01.y), w01, a2);
    a01 = __hfma2(*reinterpret_cast<__half2*>(&v11.x), w11, a01);
    a2  = __hfma2(*reinterpret_cast<__half2*>(&v11.y), w11, a2);
}

__device__ __forceinline__ float pixel_mse(const uint2* __restrict__ img,
                                           float Xp, float Yp, float Zp,
                                           float Xt, float Yt, float Zt) {
    __half2 p01, p2, t01, t2;
    sample3h(img, Xp, Yp, Zp, p01, p2);
    sample3h(img, Xt, Yt, Zt, t01, t2);
    __half2 d01 = __hsub2(p01, t01);
    __half2 d2  = __hsub2(p2, t2);
    float2 f = __half22float2(d01);
    float  g = __low2float(d2);
    return fmaf(f.x, f.x, fmaf(f.y, f.y, g * g));
}

// ---------------------------------------------------------------------------
// Main kernel (chunked): block = (batch, 4-row band); thread t handles
// x = t and x = t+256 for each of the 4 rows (8 pixels)
// ---------------------------------------------------------------------------
__global__ void __launch_bounds__(THREADS, 7)
pl_kernel(const float* __restrict__ Hp, const float* __restrict__ Ht,
          float* __restrict__ out, int chunk) {
    __shared__ float shp[9];
    __shared__ float sht[9];
    __shared__ float s_part[THREADS / 32];

    int tid = threadIdx.x;
    int gbid = chunk * MAIN_BLOCKS_CHUNK + blockIdx.x;
    int b  = gbid >> 7;                 // 128 bands per batch
    int y0 = (gbid & 127) << 2;

    if (tid == 0) invert3x3s(Hp + b * 9, shp);
    if (tid == 1) invert3x3s(Ht + b * 9, sht);
    __syncthreads();

    float fx = (float)tid, fy = (float)y0;

    float Xp = fmaf(shp[0], fx, fmaf(shp[1], fy, shp[2]));
    float Yp = fmaf(shp[3], fx, fmaf(shp[4], fy, shp[5]));
    float Zp = fmaf(shp[6], fx, fmaf(shp[7], fy, shp[8]));
    float Xt = fmaf(sht[0], fx, fmaf(sht[1], fy, sht[2]));
    float Yt = fmaf(sht[3], fx, fmaf(sht[4], fy, sht[5]));
    float Zt = fmaf(sht[6], fx, fmaf(sht[7], fy, sht[8]));

    float dXp = shp[0] * 256.0f, dYp = shp[3] * 256.0f, dZp = shp[6] * 256.0f;
    float dXt = sht[0] * 256.0f, dYt = sht[3] * 256.0f, dZt = sht[6] * 256.0f;

    const uint2* img = reinterpret_cast<const uint2*>(g_img) + (size_t)b * PPLANE;

    float acc = 0.0f;
#pragma unroll
    for (int r = 0; r < ROWS_PER_BLOCK; r++) {
        acc += pixel_mse(img, Xp, Yp, Zp, Xt, Yt, Zt);
        acc += pixel_mse(img, Xp + dXp, Yp + dYp, Zp + dZp,
                              Xt + dXt, Yt + dYt, Zt + dZt);
        if (r < ROWS_PER_BLOCK - 1) {
            Xp += shp[1]; Yp += shp[4]; Zp += shp[7];
            Xt += sht[1]; Yt += sht[4]; Zt += sht[7];
        }
    }

#pragma unroll
    for (int off = 16; off > 0; off >>= 1)
        acc += __shfl_down_sync(0xFFFFFFFFu, acc, off);

    int lane = tid & 31, wid = tid >> 5;
    if (lane == 0) s_part[wid] = acc;
    __syncthreads();
    if (tid == 0) {
        float v = 0.0f;
#pragma unroll
        for (int i = 0; i < THREADS / 32; i++) v += s_part[i];
        atomicAdd(&g_acc, v * INV_NELEM);
        __threadfence();
        unsigned t = atomicInc(&g_ticket, NBLOCKS - 1);   // counts ALL chunks
        if (t == NBLOCKS - 1) {
            float r = atomicExch(&g_acc, 0.0f);
            out[0] = r;
        }
    }
}

// ---------------------------------------------------------------------------
// Launch: fork-join pipeline. Prepass chunks on a side stream overlap main
// chunks on the capture (legacy) stream; main chunk c waits on prepass c.
// Stream/events are host-side resources created once; launched work is
// identical every call (deterministic, graph-capturable).
// ---------------------------------------------------------------------------
extern "C" void kernel_launch(void* const* d_in, const int* in_sizes, int n_in,
                              void* d_out, int out_size) {
    const float* Hp = (const float*)d_in[0];
    const float* Ht = (const float*)d_in[1];
    const float* I  = (const float*)d_in[2];
    float* out = (float*)d_out;

    static cudaStream_t side = nullptr;
    static cudaEvent_t  evFork;
    static cudaEvent_t  evPre[NCHUNK];
    if (side == nullptr) {
        cudaStreamCreateWithFlags(&side, cudaStreamNonBlocking);
        cudaEventCreateWithFlags(&evFork, cudaEventDisableTiming);
        for (int c = 0; c < NCHUNK; c++)
            cudaEventCreateWithFlags(&evPre[c], cudaEventDisableTiming);
    }

    // fork: side stream joins the capture via event wait
    cudaEventRecord(evFork, 0);
    cudaStreamWaitEvent(side, evFork, 0);

    for (int c = 0; c < NCHUNK; c++) {
        interleave_kernel<<<PRE_BLOCKS_CHUNK, THREADS, 0, side>>>(I, c);
        cudaEventRecord(evPre[c], side);
    }
    for (int c = 0; c < NCHUNK; c++) {
        cudaStreamWaitEvent(0, evPre[c], 0);   // join chunk c into main stream
        pl_kernel<<<MAIN_BLOCKS_CHUNK, THREADS>>>(Hp, Ht, out, c);
    }
}

// round 11
// speedup vs baseline: 1.7010x; 1.7010x over previous
#include <cuda_runtime.h>
#include <cuda_fp16.h>

#define BATCH     32
#define CHANNELS  3
#define HIMG      512
#define WIMG      512
#define PLANE     (HIMG * WIMG)
#define PXTOT     (BATCH * PLANE)
#define THREADS   256
#define ROWS_PER_BLOCK 4
#define NBLOCKS   (BATCH * HIMG / ROWS_PER_BLOCK)   // 4096
#define INV_NELEM (1.0f / (float)(BATCH * CHANNELS * HIMG * WIMG))

// Texture-backed image: batches stacked vertically, 514 rows per batch
// (1 zero pad row on top of each batch; batch b image rows = b*514+1 .. +512;
// the next batch's pad row doubles as b's bottom pad). +1 final pad row.
// x out-of-range handled by cudaAddressModeBorder. Pads never written;
// __device__ globals zero-init at module load -> permanent zeros.
#define BROWS     514
#define TEXROWS   (BATCH * BROWS + 1)               // 16449
__device__ __half2      g_img[TEXROWS * WIMG * 2];  // half4 per texel, ~67.4MB
__device__ float        g_acc;
__device__ unsigned int g_ticket;

// ---------------------------------------------------------------------------
// Prepass: planar fp32 [B,3,H,W] -> stacked interleaved fp16x4 texture rows
// ---------------------------------------------------------------------------
__global__ void __launch_bounds__(THREADS)
interleave_kernel(const float* __restrict__ I) {
    int t   = blockIdx.x * blockDim.x + threadIdx.x;   // < PXTOT/4
    int px  = t << 2;
    int b   = px >> 18;
    int off = px & (PLANE - 1);
    int y   = off >> 9;
    int x   = off & (WIMG - 1);
    const float* base = I + (size_t)b * (CHANNELS * PLANE) + off;
    float4 c0 = *(const float4*)(base);
    float4 c1 = *(const float4*)(base + PLANE);
    float4 c2 = *(const float4*)(base + 2 * PLANE);

    __half2 o[8];
    o[0] = __floats2half2_rn(c0.x, c1.x);
    o[1] = __floats2half2_rn(c2.x, 0.0f);
    o[2] = __floats2half2_rn(c0.y, c1.y);
    o[3] = __floats2half2_rn(c2.y, 0.0f);
    o[4] = __floats2half2_rn(c0.z, c1.z);
    o[5] = __floats2half2_rn(c2.z, 0.0f);
    o[6] = __floats2half2_rn(c0.w, c1.w);
    o[7] = __floats2half2_rn(c2.w, 0.0f);

    size_t dpx = ((size_t)b * BROWS + 1 + y) * WIMG + x;
    uint4* dst = reinterpret_cast<uint4*>(g_img + dpx * 2);
    dst[0] = *reinterpret_cast<uint4*>(&o[0]);
    dst[1] = *reinterpret_cast<uint4*>(&o[4]);
}

// ---------------------------------------------------------------------------
// 3x3 inverse via adjugate; X,Y rows prescaled by W/(W-1)
// ---------------------------------------------------------------------------
#define CSCALE (512.0f / 511.0f)

__device__ __forceinline__ void invert3x3s(const float* __restrict__ m,
                                           float* __restrict__ inv) {
    float c00 = m[4] * m[8] - m[5] * m[7];
    float c01 = m[5] * m[6] - m[3] * m[8];
    float c02 = m[3] * m[7] - m[4] * m[6];
    float det = m[0] * c00 + m[1] * c01 + m[2] * c02;
    float id  = CSCALE / det;
    float idz = 1.0f / det;
    inv[0] = c00 * id;
    inv[1] = (m[2] * m[7] - m[1] * m[8]) * id;
    inv[2] = (m[1] * m[5] - m[2] * m[4]) * id;
    inv[3] = c01 * id;
    inv[4] = (m[0] * m[8] - m[2] * m[6]) * id;
    inv[5] = (m[2] * m[3] - m[0] * m[5]) * id;
    inv[6] = c02 * idz;
    inv[7] = (m[1] * m[6] - m[0] * m[7]) * idz;
    inv[8] = (m[0] * m[4] - m[1] * m[3]) * idz;
}

__device__ __forceinline__ float frcp(float x) {
    float r;
    asm("rcp.approx.f32 %0, %1;" : "=f"(r) : "f"(x));
    return r;
}

// ---------------------------------------------------------------------------
// One warped sample: coords + single bilinear tex fetch (filter in TEX pipe).
// Texel centers at +0.5 => texture coord = pixel coord + 0.5; our sample pos
// sx = X/Z - 0.5, so tex x = X/Z exactly. y adds the batch row base.
// Clamps map NaN/inf (Z~0) into the pad/border zone deterministically;
// clamp range keeps all taps within this batch's pad rows.
// ---------------------------------------------------------------------------
__device__ __forceinline__ float4 sample_tex(cudaTextureObject_t tex,
                                             float ybase,
                                             float X, float Y, float Z) {
    float iz = frcp(Z);
    float xs = X * iz;
    float ys = fmaf(Y, iz, ybase);
    xs = fminf(fmaxf(xs, -1.5f), 513.5f);
    ys = fminf(fmaxf(ys, ybase - 1.5f), ybase + 513.5f);
    return tex2D<float4>(tex, xs, ys);
}

// ---------------------------------------------------------------------------
// Main kernel: block = (batch, 4-row band); thread t handles
// x = t and x = t+256 for each of the 4 rows (8 pixels)
// ---------------------------------------------------------------------------
__global__ void __launch_bounds__(THREADS)
pl_kernel(const float* __restrict__ Hp, const float* __restrict__ Ht,
          float* __restrict__ out, cudaTextureObject_t tex) {
    __shared__ float shp[9];
    __shared__ float sht[9];
    __shared__ float s_part[THREADS / 32];

    int tid = threadIdx.x;
    int b  = blockIdx.x >> 7;                 // 128 bands per batch
    int y0 = (blockIdx.x & 127) << 2;

    if (tid == 0) invert3x3s(Hp + b * 9, shp);
    if (tid == 1) invert3x3s(Ht + b * 9, sht);
    __syncthreads();

    float fx = (float)tid, fy = (float)y0;
    float ybase = (float)(b * BROWS + 1);     // image row 0 of this batch

    float Xp = fmaf(shp[0], fx, fmaf(shp[1], fy, shp[2]));
    float Yp = fmaf(shp[3], fx, fmaf(shp[4], fy, shp[5]));
    float Zp = fmaf(shp[6], fx, fmaf(shp[7], fy, shp[8]));
    float Xt = fmaf(sht[0], fx, fmaf(sht[1], fy, sht[2]));
    float Yt = fmaf(sht[3], fx, fmaf(sht[4], fy, sht[5]));
    float Zt = fmaf(sht[6], fx, fmaf(sht[7], fy, sht[8]));

    float dXp = shp[0] * 256.0f, dYp = shp[3] * 256.0f, dZp = shp[6] * 256.0f;
    float dXt = sht[0] * 256.0f, dYt = sht[3] * 256.0f, dZt = sht[6] * 256.0f;

    float acc = 0.0f;
#pragma unroll
    for (int r = 0; r < ROWS_PER_BLOCK; r++) {
        {
            float4 p = sample_tex(tex, ybase, Xp, Yp, Zp);
            float4 t = sample_tex(tex, ybase, Xt, Yt, Zt);
            float d0 = p.x - t.x, d1 = p.y - t.y, d2 = p.z - t.z;
            acc = fmaf(d0, d0, acc);
            acc = fmaf(d1, d1, acc);
            acc = fmaf(d2, d2, acc);
        }
        {
            float4 p = sample_tex(tex, ybase, Xp + dXp, Yp + dYp, Zp + dZp);
            float4 t = sample_tex(tex, ybase, Xt + dXt, Yt + dYt, Zt + dZt);
            float d0 = p.x - t.x, d1 = p.y - t.y, d2 = p.z - t.z;
            acc = fmaf(d0, d0, acc);
            acc = fmaf(d1, d1, acc);
            acc = fmaf(d2, d2, acc);
        }
        if (r < ROWS_PER_BLOCK - 1) {
            Xp += shp[1]; Yp += shp[4]; Zp += shp[7];
            Xt += sht[1]; Yt += sht[4]; Zt += sht[7];
        }
    }

#pragma unroll
    for (int off = 16; off > 0; off >>= 1)
        acc += __shfl_down_sync(0xFFFFFFFFu, acc, off);

    int lane = tid & 31, wid = tid >> 5;
    if (lane == 0) s_part[wid] = acc;
    __syncthreads();
    if (tid == 0) {
        float v = 0.0f;
#pragma unroll
        for (int i = 0; i < THREADS / 32; i++) v += s_part[i];
        atomicAdd(&g_acc, v * INV_NELEM);
        __threadfence();
        unsigned t = atomicInc(&g_ticket, NBLOCKS - 1);   // wraps -> self-reset
        if (t == NBLOCKS - 1) {
            float r = atomicExch(&g_acc, 0.0f);
            out[0] = r;
        }
    }
}

// ---------------------------------------------------------------------------
// Launch: serial prepass -> main (overlap proven counterproductive: prepass
// saturates chip-wide LTS). Texture object is a one-time host-side
// descriptor over the static __device__ array (no device allocation).
// ---------------------------------------------------------------------------
extern "C" void kernel_launch(void* const* d_in, const int* in_sizes, int n_in,
                              void* d_out, int out_size) {
    const float* Hp = (const float*)d_in[0];
    const float* Ht = (const float*)d_in[1];
    const float* I  = (const float*)d_in[2];
    float* out = (float*)d_out;

    static cudaTextureObject_t tex = 0;
    if (tex == 0) {
        void* ptr = nullptr;
        cudaGetSymbolAddress(&ptr, g_img);
        cudaResourceDesc rd;
        memset(&rd, 0, sizeof(rd));
        rd.resType = cudaResourceTypePitch2D;
        rd.res.pitch2D.devPtr = ptr;
        rd.res.pitch2D.desc = cudaCreateChannelDesc(16, 16, 16, 16,
                                                    cudaChannelFormatKindFloat);
        rd.res.pitch2D.width = WIMG;
        rd.res.pitch2D.height = TEXROWS;
        rd.res.pitch2D.pitchInBytes = WIMG * 8;
        cudaTextureDesc td;
        memset(&td, 0, sizeof(td));
        td.addressMode[0] = cudaAddressModeBorder;
        td.addressMode[1] = cudaAddressModeBorder;
        td.filterMode = cudaFilterModeLinear;
        td.readMode = cudaReadModeElementType;
        td.normalizedCoords = 0;
        cudaCreateTextureObject(&tex, &rd, &td, nullptr);
    }

    interleave_kernel<<<PXTOT / 4 / THREADS, THREADS>>>(I);
    pl_kernel<<<NBLOCKS, THREADS>>>(Hp, Ht, out, tex);
}